// round 6
// baseline (speedup 1.0000x reference)
#include <cuda_runtime.h>
#include <cuda_bf16.h>
#include <cstdint>

// Problem constants
#define BB 8192
#define NN 128
#define HH 1024
#define OO 64      // 2*A
#define AA 32
#define TT 8

#define BH ((size_t)BB * HH)
#define BO ((size_t)BB * OO)

// ---------------------------------------------------------------------------
// Scratch (device globals — allocation-free per harness rules)
// ---------------------------------------------------------------------------
__device__ signed char    g_s1all[TT * BH];      // s1 spikes for all 8 steps (0/1 s8)
__device__ float          g_x2   [TT * BH];      // s1@w2 for all 8 steps
__device__ unsigned short g_sacc [BH];           // sum_t 2^(t-8) s2(t), bf16 (exact)
__device__ float          g_v3   [BO];
__device__ signed char    g_w2q[3 * 1024 * 1024]; // [digit][N=1024][K=1024] s8
__device__ unsigned short g_w3t[64 * 3072];      // [N=64][K=3072] bf16 hi|mid|lo
__device__ float          g_b3s[OO];             // b3 * 255/256

// ---------------------------------------------------------------------------
// PTX helpers (baseline sm_103 ISA: cp.async, ldmatrix, mma.sync)
// ---------------------------------------------------------------------------
__device__ __forceinline__ uint32_t smem_u32(const void* p) {
    uint32_t a;
    asm("{ .reg .u64 t; cvta.to.shared.u64 t, %1; cvt.u32.u64 %0, t; }" : "=r"(a) : "l"(p));
    return a;
}
__device__ __forceinline__ void cp16(uint32_t dst, const void* src) {
    asm volatile("cp.async.cg.shared.global [%0], [%1], 16;" :: "r"(dst), "l"(src));
}
#define CP_COMMIT() asm volatile("cp.async.commit_group;" ::: "memory")
#define CP_WAIT(n)  asm volatile("cp.async.wait_group %0;" :: "n"(n) : "memory")

__device__ __forceinline__ void ldsm4(uint32_t* r, uint32_t a) {
    asm volatile("ldmatrix.sync.aligned.m8n8.x4.shared.b16 {%0,%1,%2,%3}, [%4];"
                 : "=r"(r[0]), "=r"(r[1]), "=r"(r[2]), "=r"(r[3]) : "r"(a));
}
// bf16 HMMA (used by the small g3 GEMM)
__device__ __forceinline__ void mma16816(float* c, const uint32_t* a, const uint32_t* b) {
    asm volatile("mma.sync.aligned.m16n8k16.row.col.f32.bf16.bf16.f32 "
                 "{%0,%1,%2,%3}, {%4,%5,%6,%7}, {%8,%9}, {%0,%1,%2,%3};"
                 : "+f"(c[0]), "+f"(c[1]), "+f"(c[2]), "+f"(c[3])
                 : "r"(a[0]), "r"(a[1]), "r"(a[2]), "r"(a[3]), "r"(b[0]), "r"(b[1]));
}
// s8 IMMA, k=32, exact s32 accumulation
__device__ __forceinline__ void imma16832(int* c, const uint32_t* a, const uint32_t* b) {
    asm volatile("mma.sync.aligned.m16n8k32.row.col.s32.s8.s8.s32 "
                 "{%0,%1,%2,%3}, {%4,%5,%6,%7}, {%8,%9}, {%0,%1,%2,%3};"
                 : "+r"(c[0]), "+r"(c[1]), "+r"(c[2]), "+r"(c[3])
                 : "r"(a[0]), "r"(a[1]), "r"(a[2]), "r"(a[3]), "r"(b[0]), "r"(b[1]));
}

// ---------------------------------------------------------------------------
// Weight prep for w2: 3-digit signed base-256 fixed point, scale 2^23.
// w2q[d][n][k], K-major.  round(w*2^23) = d1*65536 + d2*256 + d3 exactly.
// ---------------------------------------------------------------------------
__global__ void prep_w2q(const float* __restrict__ w2) {
    int t = blockIdx.x * blockDim.x + threadIdx.x;           // 1M threads
    if (t >= 1024 * 1024) return;
    int n = t & 1023, k = t >> 10;
    float w = w2[(size_t)k * 1024 + n];
    int W = __float2int_rn(w * 8388608.0f);                  // |W| < 2^21 for these weights
    int d3 = (W << 24) >> 24;
    int W1 = (W - d3) >> 8;
    int d2 = (W1 << 24) >> 24;
    int d1 = (W1 - d2) >> 8;                                 // |d1| small, fits s8
    size_t idx = (size_t)n * 1024 + k;
    g_w2q[idx]                 = (signed char)d1;
    g_w2q[1048576 + idx]       = (signed char)d2;
    g_w2q[2097152 + idx]       = (signed char)d3;
}

// ---------------------------------------------------------------------------
// Weight prep for w3: bf16 3-term split (unchanged, small GEMM)
// ---------------------------------------------------------------------------
__global__ void prep_w3t(const float* __restrict__ w3, const float* __restrict__ b3) {
    int t = blockIdx.x * blockDim.x + threadIdx.x;           // 64K threads
    if (t >= 64 * 1024) return;
    int n = t & 63, k = t >> 6;
    float w = w3[(size_t)k * 64 + n];
    __nv_bfloat16 hi = __float2bfloat16(w);
    float r1 = w - __bfloat162float(hi);
    __nv_bfloat16 mid = __float2bfloat16(r1);
    __nv_bfloat16 lo  = __float2bfloat16(r1 - __bfloat162float(mid));
    size_t base = (size_t)n * 3072;
    g_w3t[base + k]        = __bfloat16_as_ushort(hi);
    g_w3t[base + 1024 + k] = __bfloat16_as_ushort(mid);
    g_w3t[base + 2048 + k] = __bfloat16_as_ushort(lo);
    if (t < OO) g_b3s[t] = b3[t] * (255.0f / 256.0f);
}

// ---------------------------------------------------------------------------
// g1 + fire1 fused: u = state@w1 + b1 (fp32 SIMT, k-ascending — bit-identical),
// then all 8 IF-node-1 steps in the epilogue, writing 8 s1 planes (s8 0/1).
// ---------------------------------------------------------------------------
__global__ __launch_bounds__(256)
void g1_fire1(const float* __restrict__ A, const float* __restrict__ Bm,
              const float* __restrict__ bias)
{
    constexpr int BM = 128, BN = 64, BK = 32, TM = 8, TN = 4;
    __shared__ float As[BM][BK + 1];
    __shared__ float Bs[BK][BN + 4];
    const int tid = threadIdx.x;
    const int tx = tid % (BN / TN);
    const int ty = tid / (BN / TN);
    const int rowBase = blockIdx.y * BM;
    const int colBase = blockIdx.x * BN;

    float acc[TM][TN];
#pragma unroll
    for (int i = 0; i < TM; i++)
#pragma unroll
        for (int j = 0; j < TN; j++) acc[i][j] = 0.0f;

    for (int k0 = 0; k0 < NN; k0 += BK) {
#pragma unroll
        for (int t = tid; t < BM * BK; t += 256) {
            int r = t >> 5, c = t & 31;
            As[r][c] = A[(size_t)(rowBase + r) * NN + (k0 + c)];
        }
#pragma unroll
        for (int t = tid; t < BK * BN; t += 256) {
            int r = t >> 6, c = t & 63;
            Bs[r][c] = Bm[(size_t)(k0 + r) * HH + (colBase + c)];
        }
        __syncthreads();
#pragma unroll
        for (int kk = 0; kk < BK; kk++) {
            float ra[TM], rb[TN];
#pragma unroll
            for (int i = 0; i < TM; i++) ra[i] = As[ty * TM + i][kk];
#pragma unroll
            for (int j = 0; j < TN; j++) rb[j] = Bs[kk][tx * TN + j];
#pragma unroll
            for (int i = 0; i < TM; i++)
#pragma unroll
                for (int j = 0; j < TN; j++)
                    acc[i][j] += ra[i] * rb[j];
        }
        __syncthreads();
    }

#pragma unroll
    for (int i = 0; i < TM; i++) {
        int r = rowBase + ty * TM + i;
#pragma unroll
        for (int j = 0; j < TN; j++) {
            int c = colBase + tx * TN + j;
            float u = acc[i][j] + bias[c];
            size_t idx = (size_t)r * HH + c;
            float v1 = 0.0f;
#pragma unroll
            for (int t = 0; t < TT; ++t) {
                float h = v1 + u;
                bool s = (h >= 1.0f);
                v1 = s ? 0.0f : h;
                g_s1all[(size_t)t * BH + idx] = s ? 1 : 0;
            }
        }
    }
}

// ---------------------------------------------------------------------------
// Big s8 IMMA GEMM: X2[65536][1024] = s1all @ w2  via 3-digit decomposition.
// Exact s32 accumulation per digit per k-chunk; digits folded into fp32 with
// power-of-2 scales.  BM=128, BN=128, chunk=128 k, 512 threads, 3 stages.
// ---------------------------------------------------------------------------
__global__ __launch_bounds__(512)
void gemm_big_s8(const signed char* __restrict__ A,
                 const signed char* __restrict__ Bq,
                 float* __restrict__ outp)
{
    constexpr int BM = 128, BN = 128;
    constexpr int NCH = 8;                // 1024 / 128
    constexpr int STAGES = 3;
    constexpr int ATB = BM * 128;         // 16384
    constexpr int BTB = 3 * BN * 128;     // 49152 (3 digit tiles)
    constexpr int STAGE = ATB + BTB;      // 65536

    extern __shared__ char dsm[];
    const uint32_t sbase = smem_u32(dsm);

    const int tid = threadIdx.x;
    const int wid = tid >> 5;
    const int lane = tid & 31;
    const int wm = wid & 3;               // M: wm*32
    const int wn = wid >> 2;              // N: wn*32
    const int rowBase = blockIdx.y * BM;
    const int colBase = blockIdx.x * BN;

    auto load_tile = [&](int buf, int ch) {
        const uint32_t sA = sbase + buf * STAGE;
        const uint32_t sB = sA + ATB;
        const int kA = ch * 128;
        // A: 128 rows x 8 chunks of 16B = 1024 / 512 = 2 per thread
#pragma unroll
        for (int i = 0; i < 2; ++i) {
            int idx = i * 512 + tid;
            int r = idx >> 3, q = idx & 7;
            const void* src = A + (size_t)(rowBase + r) * 1024 + kA + q * 16;
            cp16(sA + r * 128 + ((q ^ (r & 7)) << 4), src);
        }
        // B: 3 digits x 128 rows x 8 chunks = 3072 / 512 = 6 per thread
#pragma unroll
        for (int i = 0; i < 6; ++i) {
            int idx = i * 512 + tid;
            int d = idx >> 10;
            int rem = idx & 1023;
            int r = rem >> 3, q = rem & 7;
            const void* src = Bq + (size_t)d * 1048576
                              + (size_t)(colBase + r) * 1024 + kA + q * 16;
            cp16(sB + d * 16384 + r * 128 + ((q ^ (r & 7)) << 4), src);
        }
    };

    float accF[2][4][4];
#pragma unroll
    for (int mt = 0; mt < 2; ++mt)
#pragma unroll
        for (int nt = 0; nt < 4; ++nt)
#pragma unroll
            for (int x = 0; x < 4; ++x) accF[mt][nt][x] = 0.0f;

#pragma unroll
    for (int p = 0; p < STAGES - 1; ++p) { load_tile(p, p); CP_COMMIT(); }

    const int rA0 = wm * 32 + (lane & 15);
    const int qAsel = lane >> 4;
    const int nB0 = wn * 32 + ((lane >> 4) << 3) + (lane & 7);
    const int qBsel = (lane >> 3) & 1;

    const float SC[3] = { 0.0078125f,            // 2^16 / 2^23
                          3.0517578125e-05f,     // 2^8  / 2^23
                          1.1920928955078125e-07f }; // 1 / 2^23

    for (int ch = 0; ch < NCH; ++ch) {
        CP_WAIT(1);
        __syncthreads();
        if (ch + STAGES - 1 < NCH) load_tile((ch + STAGES - 1) % STAGES, ch + STAGES - 1);
        CP_COMMIT();

        const uint32_t sA = sbase + (ch % STAGES) * STAGE;
        const uint32_t sB = sA + ATB;

#pragma unroll
        for (int d = 0; d < 3; ++d) {
            int p[2][4][4];
#pragma unroll
            for (int mt = 0; mt < 2; ++mt)
#pragma unroll
                for (int nt = 0; nt < 4; ++nt)
#pragma unroll
                    for (int x = 0; x < 4; ++x) p[mt][nt][x] = 0;

            const uint32_t sBd = sB + d * 16384;
#pragma unroll
            for (int s = 0; s < 4; ++s) {
                uint32_t a[2][4];
#pragma unroll
                for (int mt = 0; mt < 2; ++mt) {
                    int r = rA0 + mt * 16;
                    int q = 2 * s + qAsel;
                    ldsm4(a[mt], sA + r * 128 + ((q ^ (r & 7)) << 4));
                }
                uint32_t b[4][2];
#pragma unroll
                for (int j = 0; j < 4; j += 2) {
                    int n = nB0 + j * 8;
                    int q = 2 * s + qBsel;
                    uint32_t t4[4];
                    ldsm4(t4, sBd + n * 128 + ((q ^ (n & 7)) << 4));
                    b[j][0] = t4[0]; b[j][1] = t4[1];
                    b[j + 1][0] = t4[2]; b[j + 1][1] = t4[3];
                }
#pragma unroll
                for (int mt = 0; mt < 2; ++mt)
#pragma unroll
                    for (int nt = 0; nt < 4; ++nt)
                        imma16832(p[mt][nt], a[mt], b[nt]);
            }
            // fold digit into fp32 accumulator (exact I2F: |p| < 2^24)
#pragma unroll
            for (int mt = 0; mt < 2; ++mt)
#pragma unroll
                for (int nt = 0; nt < 4; ++nt)
#pragma unroll
                    for (int x = 0; x < 4; ++x)
                        accF[mt][nt][x] = fmaf(__int2float_rn(p[mt][nt][x]),
                                               SC[d], accF[mt][nt][x]);
        }
    }

    // raw fp32 store
#pragma unroll
    for (int mt = 0; mt < 2; ++mt) {
        int r0 = rowBase + wm * 32 + mt * 16 + (lane >> 2);
#pragma unroll
        for (int nt = 0; nt < 4; ++nt) {
            int c = colBase + wn * 32 + nt * 8 + (lane & 3) * 2;
#pragma unroll
            for (int hrow = 0; hrow < 2; ++hrow) {
                int r = r0 + hrow * 8;
                size_t idx = (size_t)r * HH + c;
                float2 o;
                o.x = accF[mt][nt][hrow * 2 + 0];
                o.y = accF[mt][nt][hrow * 2 + 1];
                *reinterpret_cast<float2*>(outp + idx) = o;
            }
        }
    }
}

// ---------------------------------------------------------------------------
// fire2 for ALL 8 steps: v2 register-local; accumulates weighted spike sum
// sacc = sum_t 2^(t-8) * s2(t)  (exact in bf16: value = m/256).
// ---------------------------------------------------------------------------
__global__ void fire2_all(const float* __restrict__ b2) {
    size_t i = (size_t)blockIdx.x * blockDim.x + threadIdx.x;
    if (i >= BH) return;
    float b2v = b2[i & 1023];
    float v2 = 0.0f, sacc = 0.0f;
#pragma unroll
    for (int t = 0; t < TT; ++t) {
        float x = g_x2[(size_t)t * BH + i];
        float h = v2 + x;       // (v2 + M)
        h = h + b2v;            // ... + b2   (matches reference order)
        bool s = (h >= 1.0f);
        v2 = s ? 0.0f : h;
        if (s) sacc += (float)(1 << t) * (1.0f / 256.0f);
    }
    g_sacc[i] = __bfloat16_as_ushort(__float2bfloat16(sacc));  // exact
}

// ---------------------------------------------------------------------------
// Small bf16 GEMM for g3: v3 = sacc @ w3t^T + b3s.  Unchanged from passing run.
// ---------------------------------------------------------------------------
__global__ __launch_bounds__(256)
void gemm_g3(const unsigned short* __restrict__ A,
             const unsigned short* __restrict__ Bt,
             const float* __restrict__ bias,
             float* __restrict__ outp)
{
    constexpr int BM = 128, BN = 64, BK = 64;
    constexpr int KTOT = 3072, AK = 1024;
    constexpr int NIT = KTOT / BK;
    constexpr int STAGES = 3;
    constexpr int ATB = BM * 128;
    constexpr int BTB = BN * 128;
    constexpr int STAGE = ATB + BTB;
    constexpr int WTM = 16;

    extern __shared__ char dsm[];
    const uint32_t sbase = smem_u32(dsm);

    const int tid = threadIdx.x;
    const int wid = tid >> 5;
    const int lane = tid & 31;
    const int wm = wid;
    const int rowBase = blockIdx.y * BM;

    auto load_tile = [&](int buf, int it) {
        const uint32_t sA = sbase + buf * STAGE;
        const uint32_t sB = sA + ATB;
        const int kb = it * BK;
        const int kA = kb & (AK - 1);
#pragma unroll
        for (int i = 0; i < (BM * 8) / 256; ++i) {
            int idx = i * 256 + tid;
            int r = idx >> 3, q = idx & 7;
            const void* src = A + (size_t)(rowBase + r) * AK + kA + q * 8;
            cp16(sA + r * 128 + ((q ^ (r & 7)) << 4), src);
        }
#pragma unroll
        for (int i = 0; i < (BN * 8) / 256; ++i) {
            int idx = i * 256 + tid;
            int r = idx >> 3, q = idx & 7;
            const void* src = Bt + (size_t)r * KTOT + kb + q * 8;
            cp16(sB + r * 128 + ((q ^ (r & 7)) << 4), src);
        }
    };

    float acc[8][4];
#pragma unroll
    for (int nt = 0; nt < 8; ++nt)
#pragma unroll
        for (int x = 0; x < 4; ++x) acc[nt][x] = 0.0f;

#pragma unroll
    for (int p = 0; p < STAGES - 1; ++p) { load_tile(p, p); CP_COMMIT(); }

    const int rA0 = wm * WTM + (lane & 15);
    const int qAsel = lane >> 4;
    const int nB0 = (lane >> 4) * 8 + (lane & 7);
    const int qBsel = (lane >> 3) & 1;

    for (int it = 0; it < NIT; ++it) {
        CP_WAIT(STAGES - 2);
        __syncthreads();
        if (it + STAGES - 1 < NIT) load_tile((it + STAGES - 1) % STAGES, it + STAGES - 1);
        CP_COMMIT();

        const uint32_t sA = sbase + (it % STAGES) * STAGE;
        const uint32_t sB = sA + ATB;

#pragma unroll
        for (int s = 0; s < 4; ++s) {
            uint32_t a[4];
            {
                int r = rA0;
                int q = 2 * s + qAsel;
                ldsm4(a, sA + r * 128 + ((q ^ (r & 7)) << 4));
            }
            uint32_t b[8][2];
#pragma unroll
            for (int j = 0; j < 8; j += 2) {
                int n = nB0 + j * 8;
                int q = 2 * s + qBsel;
                uint32_t t4[4];
                ldsm4(t4, sB + n * 128 + ((q ^ (n & 7)) << 4));
                b[j][0] = t4[0]; b[j][1] = t4[1];
                b[j + 1][0] = t4[2]; b[j + 1][1] = t4[3];
            }
#pragma unroll
            for (int nt = 0; nt < 8; ++nt)
                mma16816(acc[nt], a, b[nt]);
        }
    }

    int r0 = rowBase + wm * WTM + (lane >> 2);
#pragma unroll
    for (int nt = 0; nt < 8; ++nt) {
        int c = nt * 8 + (lane & 3) * 2;
        float bi0 = bias[c], bi1 = bias[c + 1];
#pragma unroll
        for (int hrow = 0; hrow < 2; ++hrow) {
            int r = r0 + hrow * 8;
            size_t idx = (size_t)r * OO + c;
            float2 o;
            o.x = acc[nt][hrow * 2 + 0] + bi0;
            o.y = acc[nt][hrow * 2 + 1] + bi1;
            *reinterpret_cast<float2*>(outp + idx) = o;
        }
    }
}

// ---------------------------------------------------------------------------
// Final tanh-Gaussian epilogue. One warp per batch row.
// ---------------------------------------------------------------------------
__global__ void finalize_kernel(const float* __restrict__ eps, float* __restrict__ out) {
    int warp = (blockIdx.x * blockDim.x + threadIdx.x) >> 5;
    int lane = threadIdx.x & 31;
    if (warp >= BB) return;
    const float* v3r = g_v3 + (size_t)warp * OO;
    float mu = v3r[lane];
    float ls = v3r[AA + lane];
    ls = fminf(fmaxf(ls, -20.0f), 2.0f);
    float sd = expf(ls);
    float e  = eps[(size_t)warp * AA + lane];
    float z  = mu + sd * e;
    float a  = tanhf(z);
    out[(size_t)warp * AA + lane] = a;
    float lp = -0.5f * e * e - ls - 0.91893853320467274f
               - logf(1.0f - a * a + 1e-7f);
#pragma unroll
    for (int o = 16; o > 0; o >>= 1) lp += __shfl_down_sync(0xffffffffu, lp, o);
    if (lane == 0) out[(size_t)BB * AA + warp] = lp;
}

// ---------------------------------------------------------------------------
extern "C" void kernel_launch(void* const* d_in, const int* in_sizes, int n_in,
                              void* d_out, int out_size)
{
    const float* state = (const float*)d_in[0];
    const float* w1    = (const float*)d_in[1];
    const float* b1    = (const float*)d_in[2];
    const float* w2    = (const float*)d_in[3];
    const float* b2    = (const float*)d_in[4];
    const float* w3    = (const float*)d_in[5];
    const float* b3    = (const float*)d_in[6];
    const float* eps   = (const float*)d_in[7];
    float* out = (float*)d_out;

    float* v3 = nullptr; float* x2 = nullptr;
    signed char* s1all = nullptr; signed char* w2q = nullptr;
    unsigned short* sacc = nullptr; unsigned short* w3t = nullptr;
    float* b3s = nullptr;
    cudaGetSymbolAddress((void**)&v3,    g_v3);
    cudaGetSymbolAddress((void**)&x2,    g_x2);
    cudaGetSymbolAddress((void**)&s1all, g_s1all);
    cudaGetSymbolAddress((void**)&sacc,  g_sacc);
    cudaGetSymbolAddress((void**)&w2q,   g_w2q);
    cudaGetSymbolAddress((void**)&w3t,   g_w3t);
    cudaGetSymbolAddress((void**)&b3s,   g_b3s);

    const int SMBIG = 3 * (128 * 128 + 3 * 128 * 128); // 196608
    const int SMG3  = 3 * (128 * 128 + 64 * 128);      // 73728
    cudaFuncSetAttribute(gemm_big_s8, cudaFuncAttributeMaxDynamicSharedMemorySize, SMBIG);
    cudaFuncSetAttribute(gemm_g3,     cudaFuncAttributeMaxDynamicSharedMemorySize, SMG3);

    // 1) weight prep
    prep_w2q<<<(1024 * 1024) / 256, 256>>>(w2);
    prep_w3t<<<(64 * 1024) / 256, 256>>>(w3, b3);

    // 2) g1 + all 8 fire1 steps fused (u never hits GMEM; s1 planes as s8)
    {
        dim3 grid(HH / 64, BB / 128);
        g1_fire1<<<grid, 256>>>(state, w1, b1);
    }

    // 3) ONE big s8 IMMA GEMM: X2[t,b,:] = s1(t) @ w2  (M = 65536)
    {
        dim3 grid(HH / 128, (TT * BB) / 128);
        gemm_big_s8<<<grid, 512, SMBIG>>>(s1all, w2q, x2);
    }

    // 4) all 8 fire2 steps in one scan; emits sacc = sum_t 2^(t-8) s2(t)
    fire2_all<<<(unsigned)((BH + 255) / 256), 256>>>(b2);

    // 5) ONE small GEMM: v3 = sacc @ w3 + (255/256) b3
    {
        dim3 grid(1, BB / 128);
        gemm_g3<<<grid, 256, SMG3>>>(sacc, w3t, b3s, v3);
    }

    // 6) tanh-Gaussian head
    finalize_kernel<<<BB / 8, 256>>>(eps, out);
}

// round 7
// speedup vs baseline: 3.6102x; 3.6102x over previous
#include <cuda_runtime.h>
#include <cuda_fp16.h>
#include <cstdint>

// Problem constants
#define BB 8192
#define NN 128
#define HH 1024
#define OO 64      // 2*A
#define AA 32
#define TT 8

#define BH ((size_t)BB * HH)
#define BO ((size_t)BB * OO)

// ---------------------------------------------------------------------------
// Scratch (device globals — allocation-free per harness rules)
// ---------------------------------------------------------------------------
__device__ unsigned short g_s1all[TT * BH];      // s1 spikes all 8 steps, fp16 bits
__device__ float          g_x2   [TT * BH];      // s1@w2 for all 8 steps
__device__ unsigned short g_sacc [BH];           // sum_t 2^(t-8) s2(t), fp16 (exact)
__device__ float          g_v3   [BO];
__device__ unsigned short g_w2h[1024 * 2048];    // [N=1024][K=2048] fp16 hi|lo
__device__ unsigned short g_w3h[64 * 2048];      // [N=64]  [K=2048] fp16 hi|lo
__device__ float          g_b3s[OO];             // b3 * 255/256

// ---------------------------------------------------------------------------
// PTX helpers (baseline sm_103 ISA: cp.async, ldmatrix, mma.sync fp16)
// ---------------------------------------------------------------------------
__device__ __forceinline__ uint32_t smem_u32(const void* p) {
    uint32_t a;
    asm("{ .reg .u64 t; cvta.to.shared.u64 t, %1; cvt.u32.u64 %0, t; }" : "=r"(a) : "l"(p));
    return a;
}
__device__ __forceinline__ void cp16(uint32_t dst, const void* src) {
    asm volatile("cp.async.cg.shared.global [%0], [%1], 16;" :: "r"(dst), "l"(src));
}
#define CP_COMMIT() asm volatile("cp.async.commit_group;" ::: "memory")
#define CP_WAIT(n)  asm volatile("cp.async.wait_group %0;" :: "n"(n) : "memory")

__device__ __forceinline__ void ldsm4(uint32_t* r, uint32_t a) {
    asm volatile("ldmatrix.sync.aligned.m8n8.x4.shared.b16 {%0,%1,%2,%3}, [%4];"
                 : "=r"(r[0]), "=r"(r[1]), "=r"(r[2]), "=r"(r[3]) : "r"(a));
}
// fp16 HMMA with fp32 accumulation
__device__ __forceinline__ void mma16816(float* c, const uint32_t* a, const uint32_t* b) {
    asm volatile("mma.sync.aligned.m16n8k16.row.col.f32.f16.f16.f32 "
                 "{%0,%1,%2,%3}, {%4,%5,%6,%7}, {%8,%9}, {%0,%1,%2,%3};"
                 : "+f"(c[0]), "+f"(c[1]), "+f"(c[2]), "+f"(c[3])
                 : "r"(a[0]), "r"(a[1]), "r"(a[2]), "r"(a[3]), "r"(b[0]), "r"(b[1]));
}

// ---------------------------------------------------------------------------
// Weight prep: [N][2048] fp16 K-major; 2-term split w = hi + lo
// (fp16 11-bit mantissa: residual <= 2^-22 |w| — below fp32 accum noise)
// ---------------------------------------------------------------------------
__global__ void prep_w2h(const float* __restrict__ w2) {
    int t = blockIdx.x * blockDim.x + threadIdx.x;            // 1M threads
    if (t >= 1024 * 1024) return;
    int n = t & 1023, k = t >> 10;
    float w = w2[(size_t)k * 1024 + n];
    __half hi = __float2half_rn(w);
    __half lo = __float2half_rn(w - __half2float(hi));
    size_t base = (size_t)n * 2048;
    g_w2h[base + k]        = __half_as_ushort(hi);
    g_w2h[base + 1024 + k] = __half_as_ushort(lo);
}
__global__ void prep_w3h(const float* __restrict__ w3, const float* __restrict__ b3) {
    int t = blockIdx.x * blockDim.x + threadIdx.x;            // 64K threads
    if (t >= 64 * 1024) return;
    int n = t & 63, k = t >> 6;
    float w = w3[(size_t)k * 64 + n];
    __half hi = __float2half_rn(w);
    __half lo = __float2half_rn(w - __half2float(hi));
    size_t base = (size_t)n * 2048;
    g_w3h[base + k]        = __half_as_ushort(hi);
    g_w3h[base + 1024 + k] = __half_as_ushort(lo);
    if (t < OO) g_b3s[t] = b3[t] * (255.0f / 256.0f);
}

// ---------------------------------------------------------------------------
// g1 + fire1 fused: u = state@w1 + b1 (fp32 SIMT, k-ascending — bit-identical),
// then all 8 IF-node-1 steps in the epilogue, writing 8 s1 planes (fp16 0/1).
// ---------------------------------------------------------------------------
__global__ __launch_bounds__(256)
void g1_fire1(const float* __restrict__ A, const float* __restrict__ Bm,
              const float* __restrict__ bias)
{
    constexpr int BM = 128, BN = 64, BK = 32, TM = 8, TN = 4;
    __shared__ float As[BM][BK + 1];
    __shared__ float Bs[BK][BN + 4];
    const int tid = threadIdx.x;
    const int tx = tid % (BN / TN);
    const int ty = tid / (BN / TN);
    const int rowBase = blockIdx.y * BM;
    const int colBase = blockIdx.x * BN;

    float acc[TM][TN];
#pragma unroll
    for (int i = 0; i < TM; i++)
#pragma unroll
        for (int j = 0; j < TN; j++) acc[i][j] = 0.0f;

    for (int k0 = 0; k0 < NN; k0 += BK) {
#pragma unroll
        for (int t = tid; t < BM * BK; t += 256) {
            int r = t >> 5, c = t & 31;
            As[r][c] = A[(size_t)(rowBase + r) * NN + (k0 + c)];
        }
#pragma unroll
        for (int t = tid; t < BK * BN; t += 256) {
            int r = t >> 6, c = t & 63;
            Bs[r][c] = Bm[(size_t)(k0 + r) * HH + (colBase + c)];
        }
        __syncthreads();
#pragma unroll
        for (int kk = 0; kk < BK; kk++) {
            float ra[TM], rb[TN];
#pragma unroll
            for (int i = 0; i < TM; i++) ra[i] = As[ty * TM + i][kk];
#pragma unroll
            for (int j = 0; j < TN; j++) rb[j] = Bs[kk][tx * TN + j];
#pragma unroll
            for (int i = 0; i < TM; i++)
#pragma unroll
                for (int j = 0; j < TN; j++)
                    acc[i][j] += ra[i] * rb[j];
        }
        __syncthreads();
    }

#pragma unroll
    for (int i = 0; i < TM; i++) {
        int r = rowBase + ty * TM + i;
#pragma unroll
        for (int j = 0; j < TN; j++) {
            int c = colBase + tx * TN + j;
            float u = acc[i][j] + bias[c];
            size_t idx = (size_t)r * HH + c;
            float v1 = 0.0f;
#pragma unroll
            for (int t = 0; t < TT; ++t) {
                float h = v1 + u;
                bool s = (h >= 1.0f);
                v1 = s ? 0.0f : h;
                g_s1all[(size_t)t * BH + idx] = s ? 0x3C00 : 0;   // fp16 1.0
            }
        }
    }
}

// ---------------------------------------------------------------------------
// Big fp16 HMMA GEMM: X2[65536][1024] = s1all @ w2h^T, K=2048 (A wraps mod
// 1024: hi then lo term). BM=128, BN=128, BK=64, 256 threads (8 warps 4x2),
// 3-stage cp.async pipeline, XOR-swizzled smem, raw fp32 store.
// ---------------------------------------------------------------------------
__global__ __launch_bounds__(256)
void gemm_big(const unsigned short* __restrict__ A,
              const unsigned short* __restrict__ Bt,
              float* __restrict__ outp)
{
    constexpr int BM = 128, BN = 128, BK = 64;
    constexpr int KTOT = 2048, AK = 1024;
    constexpr int NIT = KTOT / BK;        // 32
    constexpr int STAGES = 3;
    constexpr int ATB = BM * 128;         // 16384
    constexpr int BTB = BN * 128;         // 16384
    constexpr int STAGE = ATB + BTB;      // 32768

    extern __shared__ char dsm[];
    const uint32_t sbase = smem_u32(dsm);

    const int tid = threadIdx.x;
    const int wid = tid >> 5;
    const int lane = tid & 31;
    const int wm = wid & 3;               // M: wm*32
    const int wn = wid >> 2;              // N: wn*64
    const int rowBase = blockIdx.y * BM;
    const int colBase = blockIdx.x * BN;

    auto load_tile = [&](int buf, int it) {
        const uint32_t sA = sbase + buf * STAGE;
        const uint32_t sB = sA + ATB;
        const int kb = it * BK;
        const int kA = kb & (AK - 1);
#pragma unroll
        for (int i = 0; i < (BM * 8) / 256; ++i) {     // 4
            int idx = i * 256 + tid;
            int r = idx >> 3, q = idx & 7;
            const void* src = A + (size_t)(rowBase + r) * AK + kA + q * 8;
            cp16(sA + r * 128 + ((q ^ (r & 7)) << 4), src);
        }
#pragma unroll
        for (int i = 0; i < (BN * 8) / 256; ++i) {     // 4
            int idx = i * 256 + tid;
            int r = idx >> 3, q = idx & 7;
            const void* src = Bt + (size_t)(colBase + r) * KTOT + kb + q * 8;
            cp16(sB + r * 128 + ((q ^ (r & 7)) << 4), src);
        }
    };

    float acc[2][8][4];
#pragma unroll
    for (int mt = 0; mt < 2; ++mt)
#pragma unroll
        for (int nt = 0; nt < 8; ++nt)
#pragma unroll
            for (int x = 0; x < 4; ++x) acc[mt][nt][x] = 0.0f;

#pragma unroll
    for (int p = 0; p < STAGES - 1; ++p) { load_tile(p, p); CP_COMMIT(); }

    const int rA0 = wm * 32 + (lane & 15);
    const int qAsel = lane >> 4;
    const int nB0 = wn * 64 + ((lane >> 4) << 3) + (lane & 7);
    const int qBsel = (lane >> 3) & 1;

    for (int it = 0; it < NIT; ++it) {
        CP_WAIT(1);
        __syncthreads();
        if (it + STAGES - 1 < NIT) load_tile((it + STAGES - 1) % STAGES, it + STAGES - 1);
        CP_COMMIT();

        const uint32_t sA = sbase + (it % STAGES) * STAGE;
        const uint32_t sB = sA + ATB;

#pragma unroll
        for (int s = 0; s < 4; ++s) {
            uint32_t a[2][4];
#pragma unroll
            for (int mt = 0; mt < 2; ++mt) {
                int r = rA0 + mt * 16;
                int q = 2 * s + qAsel;
                ldsm4(a[mt], sA + r * 128 + ((q ^ (r & 7)) << 4));
            }
            uint32_t b[8][2];
#pragma unroll
            for (int j = 0; j < 8; j += 2) {
                int n = nB0 + j * 8;
                int q = 2 * s + qBsel;
                uint32_t t4[4];
                ldsm4(t4, sB + n * 128 + ((q ^ (n & 7)) << 4));
                b[j][0] = t4[0]; b[j][1] = t4[1];
                b[j + 1][0] = t4[2]; b[j + 1][1] = t4[3];
            }
#pragma unroll
            for (int mt = 0; mt < 2; ++mt)
#pragma unroll
                for (int nt = 0; nt < 8; ++nt)
                    mma16816(acc[mt][nt], a[mt], b[nt]);
        }
    }

    // raw fp32 store
#pragma unroll
    for (int mt = 0; mt < 2; ++mt) {
        int r0 = rowBase + wm * 32 + mt * 16 + (lane >> 2);
#pragma unroll
        for (int nt = 0; nt < 8; ++nt) {
            int c = colBase + wn * 64 + nt * 8 + (lane & 3) * 2;
#pragma unroll
            for (int hrow = 0; hrow < 2; ++hrow) {
                int r = r0 + hrow * 8;
                size_t idx = (size_t)r * HH + c;
                float2 o;
                o.x = acc[mt][nt][hrow * 2 + 0];
                o.y = acc[mt][nt][hrow * 2 + 1];
                *reinterpret_cast<float2*>(outp + idx) = o;
            }
        }
    }
}

// ---------------------------------------------------------------------------
// fire2 for ALL 8 steps: v2 register-local; accumulates weighted spike sum
// sacc = sum_t 2^(t-8) * s2(t)  (value m/256 — exact in fp16).
// ---------------------------------------------------------------------------
__global__ void fire2_all(const float* __restrict__ b2) {
    size_t i = (size_t)blockIdx.x * blockDim.x + threadIdx.x;
    if (i >= BH) return;
    float b2v = b2[i & 1023];
    float v2 = 0.0f, sacc = 0.0f;
#pragma unroll
    for (int t = 0; t < TT; ++t) {
        float x = g_x2[(size_t)t * BH + i];
        float h = v2 + x;       // (v2 + M)
        h = h + b2v;            // ... + b2   (matches reference order)
        bool s = (h >= 1.0f);
        v2 = s ? 0.0f : h;
        if (s) sacc += (float)(1 << t) * (1.0f / 256.0f);
    }
    g_sacc[i] = __half_as_ushort(__float2half_rn(sacc));  // exact
}

// ---------------------------------------------------------------------------
// Small fp16 GEMM for g3: v3 = sacc @ w3h^T + b3s.  K=2048 (hi|lo).
// ---------------------------------------------------------------------------
__global__ __launch_bounds__(256)
void gemm_g3(const unsigned short* __restrict__ A,
             const unsigned short* __restrict__ Bt,
             const float* __restrict__ bias,
             float* __restrict__ outp)
{
    constexpr int BM = 128, BN = 64, BK = 64;
    constexpr int KTOT = 2048, AK = 1024;
    constexpr int NIT = KTOT / BK;        // 32
    constexpr int STAGES = 3;
    constexpr int ATB = BM * 128;
    constexpr int BTB = BN * 128;
    constexpr int STAGE = ATB + BTB;
    constexpr int WTM = 16;

    extern __shared__ char dsm[];
    const uint32_t sbase = smem_u32(dsm);

    const int tid = threadIdx.x;
    const int wid = tid >> 5;
    const int lane = tid & 31;
    const int wm = wid;
    const int rowBase = blockIdx.y * BM;

    auto load_tile = [&](int buf, int it) {
        const uint32_t sA = sbase + buf * STAGE;
        const uint32_t sB = sA + ATB;
        const int kb = it * BK;
        const int kA = kb & (AK - 1);
#pragma unroll
        for (int i = 0; i < (BM * 8) / 256; ++i) {
            int idx = i * 256 + tid;
            int r = idx >> 3, q = idx & 7;
            const void* src = A + (size_t)(rowBase + r) * AK + kA + q * 8;
            cp16(sA + r * 128 + ((q ^ (r & 7)) << 4), src);
        }
#pragma unroll
        for (int i = 0; i < (BN * 8) / 256; ++i) {
            int idx = i * 256 + tid;
            int r = idx >> 3, q = idx & 7;
            const void* src = Bt + (size_t)r * KTOT + kb + q * 8;
            cp16(sB + r * 128 + ((q ^ (r & 7)) << 4), src);
        }
    };

    float acc[8][4];
#pragma unroll
    for (int nt = 0; nt < 8; ++nt)
#pragma unroll
        for (int x = 0; x < 4; ++x) acc[nt][x] = 0.0f;

#pragma unroll
    for (int p = 0; p < STAGES - 1; ++p) { load_tile(p, p); CP_COMMIT(); }

    const int rA0 = wm * WTM + (lane & 15);
    const int qAsel = lane >> 4;
    const int nB0 = (lane >> 4) * 8 + (lane & 7);
    const int qBsel = (lane >> 3) & 1;

    for (int it = 0; it < NIT; ++it) {
        CP_WAIT(1);
        __syncthreads();
        if (it + STAGES - 1 < NIT) load_tile((it + STAGES - 1) % STAGES, it + STAGES - 1);
        CP_COMMIT();

        const uint32_t sA = sbase + (it % STAGES) * STAGE;
        const uint32_t sB = sA + ATB;

#pragma unroll
        for (int s = 0; s < 4; ++s) {
            uint32_t a[4];
            {
                int r = rA0;
                int q = 2 * s + qAsel;
                ldsm4(a, sA + r * 128 + ((q ^ (r & 7)) << 4));
            }
            uint32_t b[8][2];
#pragma unroll
            for (int j = 0; j < 8; j += 2) {
                int n = nB0 + j * 8;
                int q = 2 * s + qBsel;
                uint32_t t4[4];
                ldsm4(t4, sB + n * 128 + ((q ^ (n & 7)) << 4));
                b[j][0] = t4[0]; b[j][1] = t4[1];
                b[j + 1][0] = t4[2]; b[j + 1][1] = t4[3];
            }
#pragma unroll
            for (int nt = 0; nt < 8; ++nt)
                mma16816(acc[nt], a, b[nt]);
        }
    }

    int r0 = rowBase + wm * WTM + (lane >> 2);
#pragma unroll
    for (int nt = 0; nt < 8; ++nt) {
        int c = nt * 8 + (lane & 3) * 2;
        float bi0 = bias[c], bi1 = bias[c + 1];
#pragma unroll
        for (int hrow = 0; hrow < 2; ++hrow) {
            int r = r0 + hrow * 8;
            size_t idx = (size_t)r * OO + c;
            float2 o;
            o.x = acc[nt][hrow * 2 + 0] + bi0;
            o.y = acc[nt][hrow * 2 + 1] + bi1;
            *reinterpret_cast<float2*>(outp + idx) = o;
        }
    }
}

// ---------------------------------------------------------------------------
// Final tanh-Gaussian epilogue. One warp per batch row.
// ---------------------------------------------------------------------------
__global__ void finalize_kernel(const float* __restrict__ eps, float* __restrict__ out) {
    int warp = (blockIdx.x * blockDim.x + threadIdx.x) >> 5;
    int lane = threadIdx.x & 31;
    if (warp >= BB) return;
    const float* v3r = g_v3 + (size_t)warp * OO;
    float mu = v3r[lane];
    float ls = v3r[AA + lane];
    ls = fminf(fmaxf(ls, -20.0f), 2.0f);
    float sd = expf(ls);
    float e  = eps[(size_t)warp * AA + lane];
    float z  = mu + sd * e;
    float a  = tanhf(z);
    out[(size_t)warp * AA + lane] = a;
    float lp = -0.5f * e * e - ls - 0.91893853320467274f
               - logf(1.0f - a * a + 1e-7f);
#pragma unroll
    for (int o = 16; o > 0; o >>= 1) lp += __shfl_down_sync(0xffffffffu, lp, o);
    if (lane == 0) out[(size_t)BB * AA + warp] = lp;
}

// ---------------------------------------------------------------------------
extern "C" void kernel_launch(void* const* d_in, const int* in_sizes, int n_in,
                              void* d_out, int out_size)
{
    const float* state = (const float*)d_in[0];
    const float* w1    = (const float*)d_in[1];
    const float* b1    = (const float*)d_in[2];
    const float* w2    = (const float*)d_in[3];
    const float* b2    = (const float*)d_in[4];
    const float* w3    = (const float*)d_in[5];
    const float* b3    = (const float*)d_in[6];
    const float* eps   = (const float*)d_in[7];
    float* out = (float*)d_out;

    float* v3 = nullptr; float* x2 = nullptr;
    unsigned short* s1all = nullptr; unsigned short* sacc = nullptr;
    unsigned short* w2h = nullptr; unsigned short* w3h = nullptr;
    float* b3s = nullptr;
    cudaGetSymbolAddress((void**)&v3,    g_v3);
    cudaGetSymbolAddress((void**)&x2,    g_x2);
    cudaGetSymbolAddress((void**)&s1all, g_s1all);
    cudaGetSymbolAddress((void**)&sacc,  g_sacc);
    cudaGetSymbolAddress((void**)&w2h,   g_w2h);
    cudaGetSymbolAddress((void**)&w3h,   g_w3h);
    cudaGetSymbolAddress((void**)&b3s,   g_b3s);

    const int SMBIG = 3 * (128 * 128 + 128 * 128); // 98304
    const int SMG3  = 3 * (128 * 128 + 64 * 128);  // 73728
    cudaFuncSetAttribute(gemm_big, cudaFuncAttributeMaxDynamicSharedMemorySize, SMBIG);
    cudaFuncSetAttribute(gemm_g3,  cudaFuncAttributeMaxDynamicSharedMemorySize, SMG3);

    // 1) weight prep (2-term fp16 split, K-major transpose)
    prep_w2h<<<(1024 * 1024) / 256, 256>>>(w2);
    prep_w3h<<<(64 * 1024) / 256, 256>>>(w3, b3);

    // 2) g1 + all 8 fire1 steps fused (u never hits GMEM; s1 planes fp16)
    {
        dim3 grid(HH / 64, BB / 128);
        g1_fire1<<<grid, 256>>>(state, w1, b1);
    }

    // 3) ONE big fp16 GEMM: X2[t,b,:] = s1(t) @ w2   (M = 65536, K = 2048)
    {
        dim3 grid(HH / 128, (TT * BB) / 128);
        gemm_big<<<grid, 256, SMBIG>>>(s1all, w2h, x2);
    }

    // 4) all 8 fire2 steps in one scan; emits sacc = sum_t 2^(t-8) s2(t)
    fire2_all<<<(unsigned)((BH + 255) / 256), 256>>>(b2);

    // 5) ONE small GEMM: v3 = sacc @ w3 + (255/256) b3
    {
        dim3 grid(1, BB / 128);
        gemm_g3<<<grid, 256, SMG3>>>(sacc, w3h, b3s, v3);
    }

    // 6) tanh-Gaussian head
    finalize_kernel<<<BB / 8, 256>>>(eps, out);
}